// round 4
// baseline (speedup 1.0000x reference)
#include <cuda_runtime.h>
#include <math.h>

#define BSZ   8
#define TSEQ  2048
#define CDIM  1024
#define HD    64

typedef unsigned long long ull;

// scratch for projected q, k, v  (4 MB each)
__device__ float g_q[BSZ * TSEQ * HD];
__device__ float g_k[BSZ * TSEQ * HD];
__device__ float g_v[BSZ * TSEQ * HD];

// ---- packed f32x2 helpers (sm_103a dual-rate fp32) -------------------------
__device__ __forceinline__ ull pk2(float lo, float hi) {
    ull r; asm("mov.b64 %0, {%1, %2};" : "=l"(r) : "f"(lo), "f"(hi)); return r;
}
__device__ __forceinline__ ull dup2(float v) { return pk2(v, v); }
__device__ __forceinline__ ull ffma2(ull a, ull b, ull c) {
    ull d; asm("fma.rn.f32x2 %0, %1, %2, %3;" : "=l"(d) : "l"(a), "l"(b), "l"(c)); return d;
}
__device__ __forceinline__ ull fmul2(ull a, ull b) {
    ull d; asm("mul.rn.f32x2 %0, %1, %2;" : "=l"(d) : "l"(a), "l"(b)); return d;
}
__device__ __forceinline__ float2 up2(ull v) {
    float lo, hi; asm("mov.b64 {%0, %1}, %2;" : "=f"(lo), "=f"(hi) : "l"(v));
    float2 f; f.x = lo; f.y = hi; return f;
}

// ---------------------------------------------------------------------------
// Kernel 1: QKV projection.  kqv = x @ W + b, bn: 0=k, 1=q, 2=v.
// M=16384, N=192(3x64), K=1024. BM=128, BN=64, BK=16, 256 threads, 8x4 tile.
// A (x) stored DUPLICATED in smem -> inner loop has zero packing MOVs:
// per k-step: 4 LDS.128 (A dup) + 1 LDS.128 (B pairs) + 16 FFMA2.
// Double-buffered smem.
// ---------------------------------------------------------------------------
__global__ __launch_bounds__(256) void qkv_proj_kernel(
    const float* __restrict__ x,
    const float* __restrict__ W,
    const float* __restrict__ b)
{
    __shared__ float As[2][16][264];   // [buf][k][2*row ^ swz]  (duplicated)
    __shared__ float Bs[2][16][68];    // [buf][k][col]

    const int bm  = blockIdx.x;
    const int bn  = blockIdx.y;
    const int tid = threadIdx.x;

    const int tr = tid >> 4;
    const int tc = tid & 15;
    const int row0 = tr * 8;
    const int col0 = tc * 4;

    const float* xblk = x + (size_t)bm * 128 * CDIM;
    const float* wblk = W + bn * 64;

    // per-thread load coordinates
    const int lr0 = tid >> 2;            // A row slice 0 (0..63)
    const int lkk = (tid & 3) * 4;       // A k-offset (0,4,8,12)
    const int bkr = tid >> 4;            // B k-row (0..15)
    const int bnc = (tid & 15) * 4;      // B col (0..60)
    const int swA = ((lkk >> 2) & 3) << 3;   // store swizzle (rows lkk..lkk+3)
    const int cA0 = (2 * lr0) ^ swA;
    const int cA1 = (2 * (lr0 + 64)) ^ swA;

    ull acc2[8][2];
#pragma unroll
    for (int i = 0; i < 8; i++) { acc2[i][0] = 0ULL; acc2[i][1] = 0ULL; }

    // ---- load chunk 0 into buffer 0 ----
    {
        float4 a0 = *reinterpret_cast<const float4*>(xblk + (size_t)lr0 * CDIM + lkk);
        float4 a1 = *reinterpret_cast<const float4*>(xblk + (size_t)(lr0 + 64) * CDIM + lkk);
        float4 bw = *reinterpret_cast<const float4*>(wblk + (size_t)bkr * 192 + bnc);
        *reinterpret_cast<ull*>(&As[0][lkk + 0][cA0]) = dup2(a0.x);
        *reinterpret_cast<ull*>(&As[0][lkk + 1][cA0]) = dup2(a0.y);
        *reinterpret_cast<ull*>(&As[0][lkk + 2][cA0]) = dup2(a0.z);
        *reinterpret_cast<ull*>(&As[0][lkk + 3][cA0]) = dup2(a0.w);
        *reinterpret_cast<ull*>(&As[0][lkk + 0][cA1]) = dup2(a1.x);
        *reinterpret_cast<ull*>(&As[0][lkk + 1][cA1]) = dup2(a1.y);
        *reinterpret_cast<ull*>(&As[0][lkk + 2][cA1]) = dup2(a1.z);
        *reinterpret_cast<ull*>(&As[0][lkk + 3][cA1]) = dup2(a1.w);
        *reinterpret_cast<float4*>(&Bs[0][bkr][bnc]) = bw;
    }
    __syncthreads();

    for (int c = 0; c < 64; c++) {
        const int cur = c & 1;
        if (c < 63) {
            const int k0 = (c + 1) * 16;
            float4 a0 = *reinterpret_cast<const float4*>(xblk + (size_t)lr0 * CDIM + k0 + lkk);
            float4 a1 = *reinterpret_cast<const float4*>(xblk + (size_t)(lr0 + 64) * CDIM + k0 + lkk);
            float4 bw = *reinterpret_cast<const float4*>(wblk + (size_t)(k0 + bkr) * 192 + bnc);
            const int nb = cur ^ 1;
            *reinterpret_cast<ull*>(&As[nb][lkk + 0][cA0]) = dup2(a0.x);
            *reinterpret_cast<ull*>(&As[nb][lkk + 1][cA0]) = dup2(a0.y);
            *reinterpret_cast<ull*>(&As[nb][lkk + 2][cA0]) = dup2(a0.z);
            *reinterpret_cast<ull*>(&As[nb][lkk + 3][cA0]) = dup2(a0.w);
            *reinterpret_cast<ull*>(&As[nb][lkk + 0][cA1]) = dup2(a1.x);
            *reinterpret_cast<ull*>(&As[nb][lkk + 1][cA1]) = dup2(a1.y);
            *reinterpret_cast<ull*>(&As[nb][lkk + 2][cA1]) = dup2(a1.z);
            *reinterpret_cast<ull*>(&As[nb][lkk + 3][cA1]) = dup2(a1.w);
            *reinterpret_cast<float4*>(&Bs[nb][bkr][bnc]) = bw;
        }

#pragma unroll
        for (int kk = 0; kk < 16; kk++) {
            const int sw = ((kk >> 2) & 3) << 3;
            const int base = (16 * tr);
            ulonglong2 A0 = *reinterpret_cast<const ulonglong2*>(&As[cur][kk][(base + 0)  ^ sw]);
            ulonglong2 A1 = *reinterpret_cast<const ulonglong2*>(&As[cur][kk][(base + 4)  ^ sw]);
            ulonglong2 A2 = *reinterpret_cast<const ulonglong2*>(&As[cur][kk][(base + 8)  ^ sw]);
            ulonglong2 A3 = *reinterpret_cast<const ulonglong2*>(&As[cur][kk][(base + 12) ^ sw]);
            ulonglong2 Bv = *reinterpret_cast<const ulonglong2*>(&Bs[cur][kk][col0]);
            acc2[0][0] = ffma2(A0.x, Bv.x, acc2[0][0]);
            acc2[0][1] = ffma2(A0.x, Bv.y, acc2[0][1]);
            acc2[1][0] = ffma2(A0.y, Bv.x, acc2[1][0]);
            acc2[1][1] = ffma2(A0.y, Bv.y, acc2[1][1]);
            acc2[2][0] = ffma2(A1.x, Bv.x, acc2[2][0]);
            acc2[2][1] = ffma2(A1.x, Bv.y, acc2[2][1]);
            acc2[3][0] = ffma2(A1.y, Bv.x, acc2[3][0]);
            acc2[3][1] = ffma2(A1.y, Bv.y, acc2[3][1]);
            acc2[4][0] = ffma2(A2.x, Bv.x, acc2[4][0]);
            acc2[4][1] = ffma2(A2.x, Bv.y, acc2[4][1]);
            acc2[5][0] = ffma2(A2.y, Bv.x, acc2[5][0]);
            acc2[5][1] = ffma2(A2.y, Bv.y, acc2[5][1]);
            acc2[6][0] = ffma2(A3.x, Bv.x, acc2[6][0]);
            acc2[6][1] = ffma2(A3.x, Bv.y, acc2[6][1]);
            acc2[7][0] = ffma2(A3.y, Bv.x, acc2[7][0]);
            acc2[7][1] = ffma2(A3.y, Bv.y, acc2[7][1]);
        }
        __syncthreads();
    }

    float bias[4];
#pragma unroll
    for (int j = 0; j < 4; j++) bias[j] = b[bn * 64 + col0 + j];

    float* outbuf = (bn == 0) ? g_k : (bn == 1) ? g_q : g_v;
#pragma unroll
    for (int i = 0; i < 8; i++) {
        float2 f0 = up2(acc2[i][0]);
        float2 f1 = up2(acc2[i][1]);
        float4 o;
        o.x = f0.x + bias[0];
        o.y = f0.y + bias[1];
        o.z = f1.x + bias[2];
        o.w = f1.y + bias[3];
        *reinterpret_cast<float4*>(
            outbuf + (size_t)(bm * 128 + row0 + i) * HD + col0) = o;
    }
}

// ---------------------------------------------------------------------------
// Kernel 2: causal flash attention.  Grid (16,8): block does q-tiles
// (bid.x, 31-bid.x) -> exactly 33 key tiles per block, 128 blocks, balanced.
// A-operands (Q, P) stored duplicated in smem; B-operands (K, V) read as
// natural pairs -> GEMM step = 3 LDS.128 + 8 FFMA2, zero packing MOVs.
// K/V global loads hoisted above the tile barrier to hide L2 latency.
// ---------------------------------------------------------------------------
__global__ __launch_bounds__(256) void attn_kernel(float* __restrict__ out)
{
    __shared__ float qd[64][132];   // [d][2r ^ swz], duplicated, pre-scaled
    __shared__ float pd[64][132];   // [j][2r ^ swz], duplicated
    __shared__ float k_s[64][64];   // [d][j ^ swz]
    __shared__ float v_s[64][64];   // [j][c] row-major

    const int tid = threadIdx.x;
    const int tr = tid >> 4, tc = tid & 15;
    const int r0 = tr * 4, c0 = tc * 4, j0 = tc * 4;
    const int bb = blockIdx.y;

    const float* kg = g_k + (size_t)bb * TSEQ * HD;
    const float* vg = g_v + (size_t)bb * TSEQ * HD;

    // per-thread loader coords (shared by q/k/v tile loads)
    // idx = it*256 + tid ; r = idx>>4 ; d = (idx&15)<<2

    for (int half = 0; half < 2; half++) {
        const int qt = half ? (31 - (int)blockIdx.x) : (int)blockIdx.x;
        const int qrow0 = qt * 64;
        const float* qg = g_q + ((size_t)bb * TSEQ + qrow0) * HD;

        __syncthreads();   // previous half's readers of qd done
#pragma unroll
        for (int it = 0; it < 4; it++) {
            int idx = it * 256 + tid;
            int r = idx >> 4;
            int d = (idx & 15) << 2;
            float4 v4 = *reinterpret_cast<const float4*>(qg + (size_t)r * HD + d);
            int cq = (2 * r) ^ (((d >> 2) & 7) << 2);
            *reinterpret_cast<ull*>(&qd[d + 0][cq]) = dup2(v4.x * 0.125f);
            *reinterpret_cast<ull*>(&qd[d + 1][cq]) = dup2(v4.y * 0.125f);
            *reinterpret_cast<ull*>(&qd[d + 2][cq]) = dup2(v4.z * 0.125f);
            *reinterpret_cast<ull*>(&qd[d + 3][cq]) = dup2(v4.w * 0.125f);
        }

        ull o2[4][2] = {{0ULL,0ULL},{0ULL,0ULL},{0ULL,0ULL},{0ULL,0ULL}};
        float m[4] = {-1e30f, -1e30f, -1e30f, -1e30f};
        float l[4] = {0.f, 0.f, 0.f, 0.f};

        for (int kt = 0; kt <= qt; kt++) {
            const int t0 = kt * 64;

            // hoisted global loads (no barrier needed to READ gmem)
            float4 kreg[4], vreg[4];
#pragma unroll
            for (int it = 0; it < 4; it++) {
                int idx = it * 256 + tid;
                int r = idx >> 4;
                int d = (idx & 15) << 2;
                kreg[it] = *reinterpret_cast<const float4*>(kg + (size_t)(t0 + r) * HD + d);
                vreg[it] = *reinterpret_cast<const float4*>(vg + (size_t)(t0 + r) * HD + d);
            }
            __syncthreads();   // prev tile's k_s/v_s readers done; qd stores visible path
#pragma unroll
            for (int it = 0; it < 4; it++) {
                int idx = it * 256 + tid;
                int r = idx >> 4;
                int d = (idx & 15) << 2;
                int sr = r ^ (((d >> 2) & 7) << 2);
                k_s[d + 0][sr] = kreg[it].x;
                k_s[d + 1][sr] = kreg[it].y;
                k_s[d + 2][sr] = kreg[it].z;
                k_s[d + 3][sr] = kreg[it].w;
                *reinterpret_cast<float4*>(&v_s[r][d]) = vreg[it];
            }
            __syncthreads();

            // ---- GEMM1: S = Q @ K^T  (column pairs; A dup'd, B natural pairs)
            ull s2[4][2] = {{0ULL,0ULL},{0ULL,0ULL},{0ULL,0ULL},{0ULL,0ULL}};
#pragma unroll 8
            for (int d = 0; d < 64; d++) {
                const int sw = ((d >> 2) & 7) << 2;
                const int ca = (2 * r0) ^ sw;
                ulonglong2 A01 = *reinterpret_cast<const ulonglong2*>(&qd[d][ca]);
                ulonglong2 A23 = *reinterpret_cast<const ulonglong2*>(&qd[d][ca ^ 4]);
                ulonglong2 Bv  = *reinterpret_cast<const ulonglong2*>(&k_s[d][j0 ^ sw]);
                s2[0][0] = ffma2(A01.x, Bv.x, s2[0][0]);
                s2[0][1] = ffma2(A01.x, Bv.y, s2[0][1]);
                s2[1][0] = ffma2(A01.y, Bv.x, s2[1][0]);
                s2[1][1] = ffma2(A01.y, Bv.y, s2[1][1]);
                s2[2][0] = ffma2(A23.x, Bv.x, s2[2][0]);
                s2[2][1] = ffma2(A23.x, Bv.y, s2[2][1]);
                s2[3][0] = ffma2(A23.y, Bv.x, s2[3][0]);
                s2[3][1] = ffma2(A23.y, Bv.y, s2[3][1]);
            }

            float s[4][4];
#pragma unroll
            for (int i = 0; i < 4; i++) {
                float2 f0 = up2(s2[i][0]);
                float2 f1 = up2(s2[i][1]);
                s[i][0] = f0.x; s[i][1] = f0.y;
                s[i][2] = f1.x; s[i][3] = f1.y;
            }

            if (kt == qt) {   // diagonal tile: causal mask
#pragma unroll
                for (int i = 0; i < 4; i++)
#pragma unroll
                    for (int j = 0; j < 4; j++)
                        if (j0 + j > r0 + i) s[i][j] = -1e30f;
            }

            // ---- streaming softmax ----
            float mn[4], corr[4];
#pragma unroll
            for (int i = 0; i < 4; i++) {
                float mx = fmaxf(fmaxf(s[i][0], s[i][1]), fmaxf(s[i][2], s[i][3]));
#pragma unroll
                for (int o = 1; o < 16; o <<= 1)
                    mx = fmaxf(mx, __shfl_xor_sync(0xffffffffu, mx, o));
                mn[i]   = fmaxf(m[i], mx);
                corr[i] = __expf(m[i] - mn[i]);
                m[i]    = mn[i];
            }

            const int swp = (tc & 7) << 2;   // = ((row>>2)&7)<<2 for rows j0..j0+3
#pragma unroll
            for (int i = 0; i < 4; i++) {
                const int cp = (2 * (r0 + i)) ^ swp;
                float r4 = 0.f;
#pragma unroll
                for (int j = 0; j < 4; j++) {
                    float e = __expf(s[i][j] - mn[i]);
                    r4 += e;
                    *reinterpret_cast<ull*>(&pd[j0 + j][cp]) = dup2(e);
                }
#pragma unroll
                for (int o = 1; o < 16; o <<= 1)
                    r4 += __shfl_xor_sync(0xffffffffu, r4, o);
                l[i] = l[i] * corr[i] + r4;
            }

#pragma unroll
            for (int i = 0; i < 4; i++) {
                ull cd = dup2(corr[i]);
                o2[i][0] = fmul2(o2[i][0], cd);
                o2[i][1] = fmul2(o2[i][1], cd);
            }
            __syncthreads();   // P visible to all

            // ---- GEMM2: O += P @ V ----
#pragma unroll 8
            for (int j = 0; j < 64; j++) {
                const int sw = ((j >> 2) & 7) << 2;
                const int ca = (2 * r0) ^ sw;
                ulonglong2 A01 = *reinterpret_cast<const ulonglong2*>(&pd[j][ca]);
                ulonglong2 A23 = *reinterpret_cast<const ulonglong2*>(&pd[j][ca ^ 4]);
                ulonglong2 Bv  = *reinterpret_cast<const ulonglong2*>(&v_s[j][c0]);
                o2[0][0] = ffma2(A01.x, Bv.x, o2[0][0]);
                o2[0][1] = ffma2(A01.x, Bv.y, o2[0][1]);
                o2[1][0] = ffma2(A01.y, Bv.x, o2[1][0]);
                o2[1][1] = ffma2(A01.y, Bv.y, o2[1][1]);
                o2[2][0] = ffma2(A23.x, Bv.x, o2[2][0]);
                o2[2][1] = ffma2(A23.x, Bv.y, o2[2][1]);
                o2[3][0] = ffma2(A23.y, Bv.x, o2[3][0]);
                o2[3][1] = ffma2(A23.y, Bv.y, o2[3][1]);
            }
        }

        // ---- finalize ----
#pragma unroll
        for (int i = 0; i < 4; i++) {
            float inv = 1.f / l[i];
            float2 f0 = up2(o2[i][0]);
            float2 f1 = up2(o2[i][1]);
            float4 o;
            o.x = f0.x * inv;
            o.y = f0.y * inv;
            o.z = f1.x * inv;
            o.w = f1.y * inv;
            *reinterpret_cast<float4*>(
                out + ((size_t)bb * TSEQ + qrow0 + r0 + i) * HD + c0) = o;
        }
    }
}

// ---------------------------------------------------------------------------
extern "C" void kernel_launch(void* const* d_in, const int* in_sizes, int n_in,
                              void* d_out, int out_size)
{
    const float* x = (const float*)d_in[0];
    const float* W = (const float*)d_in[1];
    const float* b = (const float*)d_in[2];
    float* out = (float*)d_out;

    (void)in_sizes; (void)n_in; (void)out_size;

    dim3 g1((BSZ * TSEQ) / 128, 3);
    qkv_proj_kernel<<<g1, 256>>>(x, W, b);

    dim3 g2(16, BSZ);
    attn_kernel<<<g2, 256>>>(out);
}